// round 1
// baseline (speedup 1.0000x reference)
#include <cuda_runtime.h>

#define NN 32768
#define FD 128
#define NE 262144
#define NL 64

// ---------------- scratch (device globals; no allocation) ----------------
__device__ float g_hA[NN * FD];
__device__ float g_hB[NN * FD];
__device__ float g_hw[NN * FD];
__device__ float g_dinv[NN];
__device__ float g_selfw[NN];
__device__ int   g_cnt[NN];
__device__ int   g_cur[NN];
__device__ int   g_row[NN + 1];
__device__ int   g_src[NE];
__device__ int   g_dst[NE];
__device__ int   g_csrc[NE];
__device__ float g_cw[NE];
__device__ int   g_is64;

// ---------------- setup kernels ----------------

// Detect whether edge_index buffer is int64 (odd 32-bit words of first 64
// values are all zero -> int64 little-endian high words) or int32.
__global__ void detect_kernel(const int* __restrict__ ei) {
    if (threadIdx.x == 0 && blockIdx.x == 0) {
        int odd_zero = 1;
        for (int i = 0; i < 64; i++) {
            if (ei[2 * i + 1] != 0) { odd_zero = 0; break; }
        }
        g_is64 = odd_zero;
    }
}

__global__ void zero_kernel() {
    int i = blockIdx.x * blockDim.x + threadIdx.x;
    if (i < NN) { g_cnt[i] = 0; g_cur[i] = 0; }
}

__global__ void convert_kernel(const int* __restrict__ ei) {
    int e = blockIdx.x * blockDim.x + threadIdx.x;
    if (e >= NE) return;
    if (g_is64) {
        const long long* p = (const long long*)ei;
        g_src[e] = (int)p[e];
        g_dst[e] = (int)p[NE + e];
    } else {
        g_src[e] = ei[e];
        g_dst[e] = ei[NE + e];
    }
}

__global__ void count_kernel() {
    int e = blockIdx.x * blockDim.x + threadIdx.x;
    if (e >= NE) return;
    atomicAdd(&g_cnt[g_dst[e]], 1);
}

// Single-block exclusive prefix sum over g_cnt -> g_row (32768 = 1024 * 32)
__global__ void scan_kernel() {
    __shared__ int sh[1024];
    int t = threadIdx.x;
    int base = t * 32;
    int s = 0;
#pragma unroll
    for (int i = 0; i < 32; i++) s += g_cnt[base + i];
    sh[t] = s;
    __syncthreads();
    for (int off = 1; off < 1024; off <<= 1) {
        int v = (t >= off) ? sh[t - off] : 0;
        __syncthreads();
        sh[t] += v;
        __syncthreads();
    }
    int run = (t == 0) ? 0 : sh[t - 1];
    for (int i = 0; i < 32; i++) {
        g_row[base + i] = run;
        run += g_cnt[base + i];
    }
    if (t == 1023) g_row[NN] = run;
}

__global__ void dinv_kernel() {
    int v = blockIdx.x * blockDim.x + threadIdx.x;
    if (v >= NN) return;
    float deg = (float)(g_cnt[v] + 1);   // +1 self-loop
    float di = 1.0f / sqrtf(deg);
    g_dinv[v] = di;
    g_selfw[v] = di * di;
}

__global__ void scatter_kernel() {
    int e = blockIdx.x * blockDim.x + threadIdx.x;
    if (e >= NE) return;
    int s = g_src[e];
    int d = g_dst[e];
    int pos = g_row[d] + atomicAdd(&g_cur[d], 1);
    g_csrc[pos] = s;
    g_cw[pos] = g_dinv[s] * g_dinv[d];
}

// ---------------- per-layer kernels ----------------

// C[NN,128] = A[NN,128] @ W[128,128], fp32.
// Block: 128x128 output tile, 256 threads, 8x8 per thread, K chunked by 32.
#define TM 128
#define TK 32
__global__ void __launch_bounds__(256) gemm_kernel(const float* __restrict__ x,
                                                   const float* __restrict__ W,
                                                   int layer) {
    const float* __restrict__ A =
        (layer == 0) ? x : ((layer & 1) ? g_hA : g_hB);
    float* __restrict__ C = g_hw;

    __shared__ float sA[TK][TM + 4];   // A transposed: sA[k][m]
    __shared__ float sB[TK][128];

    int mbase = blockIdx.x * TM;
    int t = threadIdx.x;
    int tx = t & 15;
    int ty = t >> 4;

    float acc[8][8];
#pragma unroll
    for (int i = 0; i < 8; i++)
#pragma unroll
        for (int j = 0; j < 8; j++) acc[i][j] = 0.0f;

    for (int k0 = 0; k0 < 128; k0 += TK) {
        // Load A chunk: 128 rows x 32 k (1024 float4)
#pragma unroll
        for (int j = 0; j < 4; j++) {
            int f = t + j * 256;
            int m = f >> 3;
            int kk = (f & 7) << 2;
            float4 v = *(const float4*)&A[(mbase + m) * 128 + k0 + kk];
            sA[kk + 0][m] = v.x;
            sA[kk + 1][m] = v.y;
            sA[kk + 2][m] = v.z;
            sA[kk + 3][m] = v.w;
        }
        // Load B chunk: 32 k x 128 cols (1024 float4)
#pragma unroll
        for (int j = 0; j < 4; j++) {
            int f = t + j * 256;
            int k = f >> 5;
            int jj = (f & 31) << 2;
            *(float4*)&sB[k][jj] = *(const float4*)&W[(k0 + k) * 128 + jj];
        }
        __syncthreads();
#pragma unroll
        for (int k = 0; k < TK; k++) {
            float a[8], b[8];
            *(float4*)&a[0] = *(const float4*)&sA[k][ty * 8];
            *(float4*)&a[4] = *(const float4*)&sA[k][ty * 8 + 4];
            *(float4*)&b[0] = *(const float4*)&sB[k][tx * 8];
            *(float4*)&b[4] = *(const float4*)&sB[k][tx * 8 + 4];
#pragma unroll
            for (int i = 0; i < 8; i++)
#pragma unroll
                for (int j = 0; j < 8; j++) acc[i][j] += a[i] * b[j];
        }
        __syncthreads();
    }
    // Store
#pragma unroll
    for (int i = 0; i < 8; i++) {
        int row = mbase + ty * 8 + i;
        *(float4*)&C[row * 128 + tx * 8]     = *(float4*)&acc[i][0];
        *(float4*)&C[row * 128 + tx * 8 + 4] = *(float4*)&acc[i][4];
    }
}

// h_out[v] = relu( selfw[v]*hw[v] + sum_e cw[e]*hw[src[e]] + bias ), warp/node
__global__ void __launch_bounds__(256) agg_kernel(const float* __restrict__ bias,
                                                  int layer) {
    int w = (blockIdx.x * blockDim.x + threadIdx.x) >> 5;
    int lane = threadIdx.x & 31;
    if (w >= NN) return;

    float* __restrict__ hout = (layer & 1) ? g_hB : g_hA;
    const float4* __restrict__ hw4 = (const float4*)g_hw;

    float sw = g_selfw[w];
    float4 v = hw4[w * 32 + lane];
    float4 acc;
    acc.x = sw * v.x; acc.y = sw * v.y; acc.z = sw * v.z; acc.w = sw * v.w;

    int beg = g_row[w];
    int end = g_row[w + 1];
    for (int e = beg; e < end; e++) {
        int s = g_csrc[e];
        float wt = g_cw[e];
        float4 u = hw4[s * 32 + lane];
        acc.x += wt * u.x;
        acc.y += wt * u.y;
        acc.z += wt * u.z;
        acc.w += wt * u.w;
    }
    float4 b = ((const float4*)bias)[lane];
    acc.x = fmaxf(acc.x + b.x, 0.0f);
    acc.y = fmaxf(acc.y + b.y, 0.0f);
    acc.z = fmaxf(acc.z + b.z, 0.0f);
    acc.w = fmaxf(acc.w + b.w, 0.0f);
    ((float4*)hout)[w * 32 + lane] = acc;
}

// out = (h + x) @ cls_w + cls_b ; warp per node
__global__ void __launch_bounds__(256) final_kernel(const float* __restrict__ x,
                                                    const float* __restrict__ cw,
                                                    const float* __restrict__ cb,
                                                    float* __restrict__ out) {
    int node = (blockIdx.x * blockDim.x + threadIdx.x) >> 5;
    int lane = threadIdx.x & 31;
    if (node >= NN) return;

    const float4* h4 = (const float4*)g_hB;   // after 64 layers (last layer odd)
    const float4* x4 = (const float4*)x;
    float4 hv = h4[node * 32 + lane];
    float4 xv = x4[node * 32 + lane];
    hv.x += xv.x; hv.y += xv.y; hv.z += xv.z; hv.w += xv.w;

    const float4* w4 = (const float4*)cw;   // cw[128][4]: each row one float4
    int f0 = lane * 4;
    float4 w0 = w4[f0], w1 = w4[f0 + 1], w2 = w4[f0 + 2], w3 = w4[f0 + 3];
    float4 p;
    p.x = hv.x * w0.x + hv.y * w1.x + hv.z * w2.x + hv.w * w3.x;
    p.y = hv.x * w0.y + hv.y * w1.y + hv.z * w2.y + hv.w * w3.y;
    p.z = hv.x * w0.z + hv.y * w1.z + hv.z * w2.z + hv.w * w3.z;
    p.w = hv.x * w0.w + hv.y * w1.w + hv.z * w2.w + hv.w * w3.w;

#pragma unroll
    for (int off = 16; off; off >>= 1) {
        p.x += __shfl_xor_sync(0xffffffffu, p.x, off);
        p.y += __shfl_xor_sync(0xffffffffu, p.y, off);
        p.z += __shfl_xor_sync(0xffffffffu, p.z, off);
        p.w += __shfl_xor_sync(0xffffffffu, p.w, off);
    }
    if (lane == 0) {
        float4 b = *(const float4*)cb;
        p.x += b.x; p.y += b.y; p.z += b.z; p.w += b.w;
        ((float4*)out)[node] = p;
    }
}

// ---------------- launch ----------------
extern "C" void kernel_launch(void* const* d_in, const int* in_sizes, int n_in,
                              void* d_out, int out_size) {
    const float* x      = (const float*)d_in[0];
    const int*   ei     = (const int*)d_in[1];     // int32 or int64; detected
    const float* wts    = (const float*)d_in[2];   // [64][128][128]
    const float* biases = (const float*)d_in[3];   // [64][128]
    const float* cls_w  = (const float*)d_in[4];   // [128][4]
    const float* cls_b  = (const float*)d_in[5];   // [4]
    float* out = (float*)d_out;

    detect_kernel<<<1, 32>>>(ei);
    zero_kernel<<<NN / 256, 256>>>();
    convert_kernel<<<NE / 256, 256>>>(ei);
    count_kernel<<<NE / 256, 256>>>();
    scan_kernel<<<1, 1024>>>();
    dinv_kernel<<<NN / 256, 256>>>();
    scatter_kernel<<<NE / 256, 256>>>();

    for (int l = 0; l < NL; l++) {
        gemm_kernel<<<NN / TM, 256>>>(x, wts + (size_t)l * 128 * 128, l);
        agg_kernel<<<NN / 8, 256>>>(biases + (size_t)l * 128, l);
    }
    final_kernel<<<NN / 8, 256>>>(x, cls_w, cls_b, out);
}

// round 3
// speedup vs baseline: 1.4838x; 1.4838x over previous
#include <cuda_runtime.h>
#include <cuda_bf16.h>
#include <cstdint>

#define NN 32768
#define FD 128
#define NE 262144
#define NL 64

// ---------------- scratch (device globals; no allocation) ----------------
__device__ float g_hA[NN * FD];
__device__ float g_hB[NN * FD];
__device__ float g_hw[NN * FD];
__device__ float g_dinv[NN];
__device__ float g_selfw[NN];
__device__ int   g_cnt[NN];
__device__ int   g_cur[NN];
__device__ int   g_row[NN + 1];
__device__ int   g_src[NE];
__device__ int   g_dst[NE];
__device__ int   g_csrc[NE];
__device__ float g_cw[NE];
__device__ int   g_is64;
// pre-split weights, transposed to [n][k] (bf16 hi / lo), per layer 128x128
__device__ __nv_bfloat16 g_wh[NL * 16384];
__device__ __nv_bfloat16 g_wl[NL * 16384];

// ---------------- helpers ----------------
__device__ __forceinline__ uint32_t smem_u32(const void* p) {
    uint32_t a;
    asm("{ .reg .u64 t; cvta.to.shared.u64 t, %1; cvt.u32.u64 %0, t; }"
        : "=r"(a) : "l"(p));
    return a;
}
__device__ __forceinline__ void ldm_x4(uint32_t* r, uint32_t addr) {
    asm volatile("ldmatrix.sync.aligned.m8n8.x4.shared.b16 {%0,%1,%2,%3}, [%4];"
                 : "=r"(r[0]), "=r"(r[1]), "=r"(r[2]), "=r"(r[3]) : "r"(addr));
}
__device__ __forceinline__ void mma16816(float* c, const uint32_t* a,
                                         uint32_t b0, uint32_t b1) {
    asm volatile(
        "mma.sync.aligned.m16n8k16.row.col.f32.bf16.bf16.f32 "
        "{%0,%1,%2,%3}, {%4,%5,%6,%7}, {%8,%9}, {%0,%1,%2,%3};"
        : "+f"(c[0]), "+f"(c[1]), "+f"(c[2]), "+f"(c[3])
        : "r"(a[0]), "r"(a[1]), "r"(a[2]), "r"(a[3]), "r"(b0), "r"(b1));
}

// ---------------- setup kernels ----------------
__global__ void detect_kernel(const int* __restrict__ ei) {
    if (threadIdx.x == 0 && blockIdx.x == 0) {
        int odd_zero = 1;
        for (int i = 0; i < 64; i++)
            if (ei[2 * i + 1] != 0) { odd_zero = 0; break; }
        g_is64 = odd_zero;
    }
}
__global__ void zero_kernel() {
    int i = blockIdx.x * blockDim.x + threadIdx.x;
    if (i < NN) { g_cnt[i] = 0; g_cur[i] = 0; }
}
__global__ void convert_kernel(const int* __restrict__ ei) {
    int e = blockIdx.x * blockDim.x + threadIdx.x;
    if (e >= NE) return;
    if (g_is64) {
        const long long* p = (const long long*)ei;
        g_src[e] = (int)p[e];
        g_dst[e] = (int)p[NE + e];
    } else {
        g_src[e] = ei[e];
        g_dst[e] = ei[NE + e];
    }
}
__global__ void count_kernel() {
    int e = blockIdx.x * blockDim.x + threadIdx.x;
    if (e >= NE) return;
    atomicAdd(&g_cnt[g_dst[e]], 1);
}
__global__ void scan_kernel() {
    __shared__ int sh[1024];
    int t = threadIdx.x;
    int base = t * 32;
    int s = 0;
#pragma unroll
    for (int i = 0; i < 32; i++) s += g_cnt[base + i];
    sh[t] = s;
    __syncthreads();
    for (int off = 1; off < 1024; off <<= 1) {
        int v = (t >= off) ? sh[t - off] : 0;
        __syncthreads();
        sh[t] += v;
        __syncthreads();
    }
    int run = (t == 0) ? 0 : sh[t - 1];
    for (int i = 0; i < 32; i++) {
        g_row[base + i] = run;
        run += g_cnt[base + i];
    }
    if (t == 1023) g_row[NN] = run;
}
__global__ void dinv_kernel() {
    int v = blockIdx.x * blockDim.x + threadIdx.x;
    if (v >= NN) return;
    float deg = (float)(g_cnt[v] + 1);
    float di = 1.0f / sqrtf(deg);
    g_dinv[v] = di;
    g_selfw[v] = di * di;
}
__global__ void scatter_kernel() {
    int e = blockIdx.x * blockDim.x + threadIdx.x;
    if (e >= NE) return;
    int s = g_src[e];
    int d = g_dst[e];
    int pos = g_row[d] + atomicAdd(&g_cur[d], 1);
    g_csrc[pos] = s;
    g_cw[pos] = g_dinv[s] * g_dinv[d];
}
// Split weights to bf16 hi/lo, transposed: g_wh[l][n][k] = hi(W[l][k][n]).
__global__ void wsplit_kernel(const float* __restrict__ wts) {
    int idx = blockIdx.x * blockDim.x + threadIdx.x;
    if (idx >= NL * 16384) return;
    int l = idx >> 14;
    int e = idx & 16383;
    int k = e >> 7;
    int n = e & 127;          // n fast: coalesced read
    float v = wts[idx];
    __nv_bfloat16 hi = __float2bfloat16(v);
    float hf = __bfloat162float(hi);
    __nv_bfloat16 lo = __float2bfloat16(v - hf);
    int o = (l << 14) + n * 128 + k;
    g_wh[o] = hi;
    g_wl[o] = lo;
}

// ---------------- HMMA GEMM: g_hw = A @ W (bf16 3-pass split) ----------------
// SMEM: sWh[128][136], sWl[128][136], sAh[128][136], sAl[128][136] (bf16)
#define PITCH 136
#define TILE_BYTES (128 * PITCH * 2)
#define OFF_WH 0
#define OFF_WL (TILE_BYTES)
#define OFF_AH (2 * TILE_BYTES)
#define OFF_AL (3 * TILE_BYTES)
#define SM_SZ  (4 * TILE_BYTES)

__global__ void __launch_bounds__(256) gemm_kernel(const float* __restrict__ x,
                                                   int layer) {
    extern __shared__ char sm[];
    __nv_bfloat16* sWh = (__nv_bfloat16*)(sm + OFF_WH);
    __nv_bfloat16* sWl = (__nv_bfloat16*)(sm + OFF_WL);
    __nv_bfloat16* sAh = (__nv_bfloat16*)(sm + OFF_AH);
    __nv_bfloat16* sAl = (__nv_bfloat16*)(sm + OFF_AL);
    uint32_t sbase = smem_u32(sm);

    int t = threadIdx.x;
    int w = t >> 5;
    int lane = t & 31;
    const float* __restrict__ A =
        (layer == 0) ? x : ((layer & 1) ? g_hA : g_hB);

    // --- load W hi/lo into padded smem (uint4 = 8 bf16) ---
    {
        const uint4* wh4 = (const uint4*)(g_wh + ((size_t)layer << 14));
        const uint4* wl4 = (const uint4*)(g_wl + ((size_t)layer << 14));
#pragma unroll
        for (int i = 0; i < 8; i++) {
            int idx8 = t + i * 256;          // 8-element chunk id
            int n = idx8 >> 4;
            int k8 = (idx8 & 15) << 3;
            *(uint4*)&sWh[n * PITCH + k8] = wh4[idx8];
            *(uint4*)&sWl[n * PITCH + k8] = wl4[idx8];
        }
    }

    int wrow = w * 16;
    int g = lane >> 2;
    int q = lane & 3;
    // ldmatrix lane address (row-major A, 272B pitch)
    uint32_t aRowOff = (uint32_t)((wrow + (lane & 15)) * (PITCH * 2) +
                                  ((lane >> 4) * 8) * 2);
    uint32_t addrAh = sbase + OFF_AH + aRowOff;
    uint32_t addrAl = sbase + OFF_AL + aRowOff;

    for (int tile = 0; tile < 2; tile++) {
        int mbase = blockIdx.x * 256 + tile * 128;

        // --- convert + split A tile into smem ---
        const float4* a4 = (const float4*)(A + (size_t)mbase * 128);
#pragma unroll 4
        for (int i = 0; i < 16; i++) {
            int f4 = t + i * 256;
            float4 v = a4[f4];
            int row = f4 >> 5;
            int c4 = f4 & 31;
            uint32_t h01, h23, l01, l23;
            asm("cvt.rn.bf16x2.f32 %0, %1, %2;" : "=r"(h01) : "f"(v.y), "f"(v.x));
            asm("cvt.rn.bf16x2.f32 %0, %1, %2;" : "=r"(h23) : "f"(v.w), "f"(v.z));
            float hx = __uint_as_float(h01 << 16);
            float hy = __uint_as_float(h01 & 0xffff0000u);
            float hz = __uint_as_float(h23 << 16);
            float hw_ = __uint_as_float(h23 & 0xffff0000u);
            asm("cvt.rn.bf16x2.f32 %0, %1, %2;" : "=r"(l01) : "f"(v.y - hy), "f"(v.x - hx));
            asm("cvt.rn.bf16x2.f32 %0, %1, %2;" : "=r"(l23) : "f"(v.w - hw_), "f"(v.z - hz));
            *(uint2*)&sAh[row * PITCH + c4 * 4] = make_uint2(h01, h23);
            *(uint2*)&sAl[row * PITCH + c4 * 4] = make_uint2(l01, l23);
        }
        __syncthreads();

        // --- main HMMA loop ---
        float acc[16][4];
#pragma unroll
        for (int i = 0; i < 16; i++)
#pragma unroll
            for (int j = 0; j < 4; j++) acc[i][j] = 0.0f;

#pragma unroll
        for (int kstep = 0; kstep < 8; kstep++) {
            uint32_t ah[4], al[4];
            ldm_x4(ah, addrAh + kstep * 32);
            ldm_x4(al, addrAl + kstep * 32);
            int kOff = kstep * 16 + q * 2;
#pragma unroll
            for (int ntp = 0; ntp < 8; ntp++) {
                int n0 = ntp * 2;
                int n1 = n0 + 1;
                const __nv_bfloat16* p0h = &sWh[(n0 * 8 + g) * PITCH + kOff];
                const __nv_bfloat16* p1h = &sWh[(n1 * 8 + g) * PITCH + kOff];
                const __nv_bfloat16* p0l = &sWl[(n0 * 8 + g) * PITCH + kOff];
                const __nv_bfloat16* p1l = &sWl[(n1 * 8 + g) * PITCH + kOff];
                uint32_t b0h0 = *(const uint32_t*)p0h;
                uint32_t b0h1 = *(const uint32_t*)(p0h + 8);
                uint32_t b1h0 = *(const uint32_t*)p1h;
                uint32_t b1h1 = *(const uint32_t*)(p1h + 8);
                uint32_t b0l0 = *(const uint32_t*)p0l;
                uint32_t b0l1 = *(const uint32_t*)(p0l + 8);
                uint32_t b1l0 = *(const uint32_t*)p1l;
                uint32_t b1l1 = *(const uint32_t*)(p1l + 8);
                mma16816(acc[n0], ah, b0h0, b0h1);
                mma16816(acc[n1], ah, b1h0, b1h1);
                mma16816(acc[n0], ah, b0l0, b0l1);
                mma16816(acc[n1], ah, b1l0, b1l1);
                mma16816(acc[n0], al, b0h0, b0h1);
                mma16816(acc[n1], al, b1h0, b1h1);
            }
        }
        __syncthreads();   // all warps done reading sA before next tile rewrites

        // --- epilogue: C fragments -> global (float2 per row-half) ---
#pragma unroll
        for (int nt = 0; nt < 16; nt++) {
            int col = nt * 8 + q * 2;
            int row0 = mbase + wrow + g;
            *(float2*)&g_hw[(size_t)row0 * 128 + col] =
                make_float2(acc[nt][0], acc[nt][1]);
            *(float2*)&g_hw[(size_t)(row0 + 8) * 128 + col] =
                make_float2(acc[nt][2], acc[nt][3]);
        }
    }
}

// ---------------- aggregation ----------------
__global__ void __launch_bounds__(256) agg_kernel(const float* __restrict__ bias,
                                                  int layer) {
    int w = (blockIdx.x * blockDim.x + threadIdx.x) >> 5;
    int lane = threadIdx.x & 31;
    if (w >= NN) return;

    float* __restrict__ hout = (layer & 1) ? g_hB : g_hA;
    const float4* __restrict__ hw4 = (const float4*)g_hw;

    float sw = g_selfw[w];
    float4 v = hw4[w * 32 + lane];
    float4 acc;
    acc.x = sw * v.x; acc.y = sw * v.y; acc.z = sw * v.z; acc.w = sw * v.w;

    int beg = g_row[w];
    int end = g_row[w + 1];
    for (int e = beg; e < end; e++) {
        int s = g_csrc[e];
        float wt = g_cw[e];
        float4 u = hw4[s * 32 + lane];
        acc.x += wt * u.x;
        acc.y += wt * u.y;
        acc.z += wt * u.z;
        acc.w += wt * u.w;
    }
    float4 b = ((const float4*)bias)[lane];
    acc.x = fmaxf(acc.x + b.x, 0.0f);
    acc.y = fmaxf(acc.y + b.y, 0.0f);
    acc.z = fmaxf(acc.z + b.z, 0.0f);
    acc.w = fmaxf(acc.w + b.w, 0.0f);
    ((float4*)hout)[w * 32 + lane] = acc;
}

// ---------------- final ----------------
__global__ void __launch_bounds__(256) final_kernel(const float* __restrict__ x,
                                                    const float* __restrict__ cw,
                                                    const float* __restrict__ cb,
                                                    float* __restrict__ out) {
    int node = (blockIdx.x * blockDim.x + threadIdx.x) >> 5;
    int lane = threadIdx.x & 31;
    if (node >= NN) return;

    const float4* h4 = (const float4*)g_hB;
    const float4* x4 = (const float4*)x;
    float4 hv = h4[node * 32 + lane];
    float4 xv = x4[node * 32 + lane];
    hv.x += xv.x; hv.y += xv.y; hv.z += xv.z; hv.w += xv.w;

    const float4* w4 = (const float4*)cw;
    int f0 = lane * 4;
    float4 w0 = w4[f0], w1 = w4[f0 + 1], w2 = w4[f0 + 2], w3 = w4[f0 + 3];
    float4 p;
    p.x = hv.x * w0.x + hv.y * w1.x + hv.z * w2.x + hv.w * w3.x;
    p.y = hv.x * w0.y + hv.y * w1.y + hv.z * w2.y + hv.w * w3.y;
    p.z = hv.x * w0.z + hv.y * w1.z + hv.z * w2.z + hv.w * w3.z;
    p.w = hv.x * w0.w + hv.y * w1.w + hv.z * w2.w + hv.w * w3.w;

#pragma unroll
    for (int off = 16; off; off >>= 1) {
        p.x += __shfl_xor_sync(0xffffffffu, p.x, off);
        p.y += __shfl_xor_sync(0xffffffffu, p.y, off);
        p.z += __shfl_xor_sync(0xffffffffu, p.z, off);
        p.w += __shfl_xor_sync(0xffffffffu, p.w, off);
    }
    if (lane == 0) {
        float4 b = *(const float4*)cb;
        p.x += b.x; p.y += b.y; p.z += b.z; p.w += b.w;
        ((float4*)out)[node] = p;
    }
}

// ---------------- launch ----------------
extern "C" void kernel_launch(void* const* d_in, const int* in_sizes, int n_in,
                              void* d_out, int out_size) {
    const float* x      = (const float*)d_in[0];
    const int*   ei     = (const int*)d_in[1];
    const float* wts    = (const float*)d_in[2];
    const float* biases = (const float*)d_in[3];
    const float* cls_w  = (const float*)d_in[4];
    const float* cls_b  = (const float*)d_in[5];
    float* out = (float*)d_out;

    cudaFuncSetAttribute(gemm_kernel, cudaFuncAttributeMaxDynamicSharedMemorySize,
                         SM_SZ);

    detect_kernel<<<1, 32>>>(ei);
    zero_kernel<<<NN / 256, 256>>>();
    convert_kernel<<<NE / 256, 256>>>(ei);
    count_kernel<<<NE / 256, 256>>>();
    scan_kernel<<<1, 1024>>>();
    dinv_kernel<<<NN / 256, 256>>>();
    scatter_kernel<<<NE / 256, 256>>>();
    wsplit_kernel<<<NL * 16384 / 256, 256>>>(wts);

    for (int l = 0; l < NL; l++) {
        gemm_kernel<<<128, 256, SM_SZ>>>(x, l);
        agg_kernel<<<NN / 8, 256>>>(biases + (size_t)l * 128, l);
    }
    final_kernel<<<NN / 8, 256>>>(x, cls_w, cls_b, out);
}